// round 4
// baseline (speedup 1.0000x reference)
#include <cuda_runtime.h>
#include <cuda_bf16.h>

// Rank-based average pooling: 2x2 window, stride 2, mean of top-2 values.
// x: [16,128,128,256] f32 NHWC  ->  out: [16,64,64,256] f32
//
// Streaming kernel at the HBM roofline (~6.5 TB/s achieved for this 4:1
// read:write mix; 312 MB irreducible traffic). One output float4 per thread,
// fully-coalesced 16B accesses, default cache ops (measured faster than .cs),
// all-32-bit indexing. Total elements fit in 32 bits (in: 2^24 f4, out: 2^22 f4).

#define C4 64          // 256 channels / 4
#define ROW_F4 8192    // 128 * 64 float4 per input row
#define COL_F4 64      // float4 per pixel

__device__ __forceinline__ float top2mean(float v0, float v1, float v2, float v3) {
    // sum of top-2 = total - smallest - second smallest
    float a = fminf(v0, v1), b = fmaxf(v0, v1);
    float c = fminf(v2, v3), d = fmaxf(v2, v3);
    float lo1 = fminf(a, c);
    float lo2 = fminf(fmaxf(a, c), fminf(b, d));
    return (v0 + v1 + v2 + v3 - lo1 - lo2) * 0.5f;
}

__global__ void __launch_bounds__(512)
rank_pool_kernel(const float4* __restrict__ in, float4* __restrict__ out) {
    unsigned idx = blockIdx.x * 512u + threadIdx.x;   // < 2^22, fits 32-bit

    // idx -> (b, ho, wo, c4); out is [16,64,64,64] in float4 units
    unsigned c4 = idx & (C4 - 1);
    unsigned t  = idx >> 6;
    unsigned wo = t & 63u;
    t >>= 6;                      // b*64 + ho
    // input base: ((b*128 + 2*ho)*128 + 2*wo)*64 + c4  =  t*2*ROW_F4 + wo*2*COL_F4 + c4
    unsigned base = t * (2u * ROW_F4) + wo * (2u * COL_F4) + c4;   // max ~2^24, fits

    float4 p00 = in[base];
    float4 p01 = in[base + COL_F4];
    float4 p10 = in[base + ROW_F4];
    float4 p11 = in[base + ROW_F4 + COL_F4];

    float4 r;
    r.x = top2mean(p00.x, p01.x, p10.x, p11.x);
    r.y = top2mean(p00.y, p01.y, p10.y, p11.y);
    r.z = top2mean(p00.z, p01.z, p10.z, p11.z);
    r.w = top2mean(p00.w, p01.w, p10.w, p11.w);

    out[idx] = r;
}

extern "C" void kernel_launch(void* const* d_in, const int* in_sizes, int n_in,
                              void* d_out, int out_size) {
    const float4* x = (const float4*)d_in[0];
    float4* o = (float4*)d_out;
    // 4,194,304 output float4s / 512 threads = 8192 blocks (exact)
    rank_pool_kernel<<<8192, 512>>>(x, o);
}